// round 1
// baseline (speedup 1.0000x reference)
#include <cuda_runtime.h>
#include <math.h>

// Problem dims
#define Q    64
#define SQ   32
#define CC   256
#define SC   256
#define H    768
#define D    128
#define QT   31          // Sq-1 tokens per query
#define CT   255         // Sc-1 tokens per doc
#define QROWS (Q*QT)     // 1984
#define CROWS (CC*CT)    // 65280
#define NROWS (QROWS+CROWS) // 67264

// Scratch: projected+normalized token embeddings, stored TRANSPOSED per batch:
//   g_qcolT[q][d][i] , g_ccolT[c][d][j]
__device__ float g_qcolT[(size_t)Q * D * QT];       // ~1.0 MB
__device__ float g_ccolT[(size_t)CC * D * CT];      // ~33.4 MB
__device__ float g_denom[Q];

// ---------------------------------------------------------------------------
// Kernel 1: pooled vectors. One block per row (64 q + 256 c). 256 threads.
// pooled = l2norm(h[:,0] * mask[:,0])
// ---------------------------------------------------------------------------
__global__ void pooled_kernel(const float* __restrict__ qh,
                              const float* __restrict__ ch,
                              const int*   __restrict__ qm,
                              const int*   __restrict__ cm,
                              float* __restrict__ out) {
    int r = blockIdx.x;
    const float* src;
    float mask;
    float* dst;
    if (r < Q) {
        src  = qh + (size_t)r * SQ * H;
        mask = (float)qm[r * SQ];
        dst  = out + Q * CC + (size_t)r * H;
    } else {
        int c = r - Q;
        src  = ch + (size_t)c * SC * H;
        mask = (float)cm[c * SC];
        dst  = out + Q * CC + Q * H + (size_t)c * H;
    }
    __shared__ float red[8];
    int t = threadIdx.x;                 // 256 threads, 768 = 3*256
    float v[3];
    float s = 0.f;
#pragma unroll
    for (int it = 0; it < 3; it++) {
        float x = src[t + it * 256] * mask;
        v[it] = x;
        s += x * x;
    }
#pragma unroll
    for (int o = 16; o; o >>= 1) s += __shfl_xor_sync(0xffffffffu, s, o);
    if ((t & 31) == 0) red[t >> 5] = s;
    __syncthreads();
    if (t < 8) {
        float ss = red[t];
#pragma unroll
        for (int o = 4; o; o >>= 1) ss += __shfl_xor_sync(0xffu, ss, o);
        if (t == 0) red[0] = ss;
    }
    __syncthreads();
    float inv = 1.f / fmaxf(sqrtf(red[0]), 1e-12f);
#pragma unroll
    for (int it = 0; it < 3; it++) dst[t + it * 256] = v[it] * inv;
}

// ---------------------------------------------------------------------------
// Kernel 2: denominators. denom[q] = sum(q_mask[q,1:])
// ---------------------------------------------------------------------------
__global__ void denom_kernel(const int* __restrict__ qm) {
    int q = threadIdx.x;
    if (q < Q) {
        int s = 0;
        for (int i = 1; i < SQ; i++) s += qm[q * SQ + i];
        g_denom[q] = (float)s;
    }
}

// ---------------------------------------------------------------------------
// Kernel 3: projection + l2norm, transposed store.
//   col[row, :] = l2norm( (h[row]*mask[row]) @ W + bias )
// Block: 32 rows x 128 cols, 256 threads (16x16), micro-tile 2M x 8N.
// K tiled by 64. ~13.2 GFLOP fp32.
// ---------------------------------------------------------------------------
#define PKT 64
__global__ void proj_kernel(const float* __restrict__ qh,
                            const float* __restrict__ ch,
                            const float* __restrict__ Wm,
                            const float* __restrict__ bias,
                            const int*   __restrict__ qm,
                            const int*   __restrict__ cm) {
    __shared__ float AsT[PKT][33];     // [k][m], padded: 8.4 KB
    __shared__ float Ws[PKT][D];       // [k][d]: 32 KB
    __shared__ float partial[32][8];
    __shared__ float invn[32];
    __shared__ const float* srcp[32];
    __shared__ float mk[32];
    __shared__ int   dbase[32];

    // Cs overlays Ws (used only after the main loop): 32*133 = 4256 <= 64*128
    float (*Cs)[133] = (float (*)[133])(&Ws[0][0]);

    int t  = threadIdx.x;
    int r0 = blockIdx.x * 32;
    bool isq = (r0 < QROWS);           // boundary 1984 is a multiple of 32

    if (t < 32) {
        int r = r0 + t;
        if (r < QROWS) {
            int q = r / QT, i = r - q * QT;
            srcp[t]  = qh + (size_t)(q * SQ + i + 1) * H;
            mk[t]    = (float)qm[q * SQ + i + 1];
            dbase[t] = q * (D * QT) + i;         // + d*QT
        } else {
            int rc = r - QROWS;
            int c = rc / CT, j = rc - c * CT;
            srcp[t]  = ch + (size_t)(c * SC + j + 1) * H;
            mk[t]    = (float)cm[c * SC + j + 1];
            dbase[t] = c * (D * CT) + j;         // + d*CT
        }
    }
    __syncthreads();

    int mg = t >> 4, ng = t & 15;
    int m0 = mg * 2, d0 = ng * 8;

    float acc[2][8];
    {
        float4 b0 = *(const float4*)(bias + d0);
        float4 b1 = *(const float4*)(bias + d0 + 4);
#pragma unroll
        for (int j = 0; j < 2; j++) {
            acc[j][0] = b0.x; acc[j][1] = b0.y; acc[j][2] = b0.z; acc[j][3] = b0.w;
            acc[j][4] = b1.x; acc[j][5] = b1.y; acc[j][6] = b1.z; acc[j][7] = b1.w;
        }
    }

    for (int kt = 0; kt < H; kt += PKT) {
        // W tile: 64x128 = 2048 float4, 8 per thread
#pragma unroll
        for (int it = 0; it < 8; it++) {
            int i4 = t + it * 256;
            int k = i4 >> 5, d4 = i4 & 31;
            float4 w = *(const float4*)(Wm + (size_t)(kt + k) * D + d4 * 4);
            *(float4*)&Ws[k][d4 * 4] = w;
        }
        // A tile (masked), stored transposed: 32x64 = 512 float4, 2 per thread
#pragma unroll
        for (int it = 0; it < 2; it++) {
            int i4 = t + it * 256;
            int m = i4 >> 4, k4 = i4 & 15;
            float4 a = *(const float4*)(srcp[m] + kt + k4 * 4);
            float mm = mk[m];
            AsT[k4 * 4 + 0][m] = a.x * mm;
            AsT[k4 * 4 + 1][m] = a.y * mm;
            AsT[k4 * 4 + 2][m] = a.z * mm;
            AsT[k4 * 4 + 3][m] = a.w * mm;
        }
        __syncthreads();
#pragma unroll 8
        for (int k = 0; k < PKT; k++) {
            float a0 = AsT[k][m0];
            float a1 = AsT[k][m0 + 1];
            float w[8];
            *(float4*)&w[0] = *(const float4*)&Ws[k][d0];
            *(float4*)&w[4] = *(const float4*)&Ws[k][d0 + 4];
#pragma unroll
            for (int jj = 0; jj < 8; jj++) {
                acc[0][jj] = fmaf(a0, w[jj], acc[0][jj]);
                acc[1][jj] = fmaf(a1, w[jj], acc[1][jj]);
            }
        }
        __syncthreads();   // also protects Ws before Cs overlay on last iter
    }

    // Epilogue: stash results, row-wise l2 norm, transposed coalesced store.
#pragma unroll
    for (int j = 0; j < 2; j++)
#pragma unroll
        for (int jj = 0; jj < 8; jj++)
            Cs[m0 + j][d0 + jj] = acc[j][jj];
    __syncthreads();
    {
        int m = t >> 3, seg = t & 7;
        float s = 0.f;
#pragma unroll
        for (int ii = 0; ii < 16; ii++) {
            float x = Cs[m][seg * 16 + ii];
            s += x * x;
        }
        partial[m][seg] = s;
    }
    __syncthreads();
    if (t < 32) {
        float s = 0.f;
#pragma unroll
        for (int seg = 0; seg < 8; seg++) s += partial[t][seg];
        invn[t] = 1.f / fmaxf(sqrtf(s), 1e-12f);
    }
    __syncthreads();
    {
        float* outbuf = isq ? g_qcolT : g_ccolT;
        int stride = isq ? QT : CT;
        int m  = t & 31;
        int dd = t >> 5;                // 8 d-lanes per pass, 16 passes
        float inv = invn[m];
        int base = dbase[m];
#pragma unroll
        for (int p = 0; p < 16; p++) {
            int d = dd + p * 8;
            outbuf[base + d * stride] = Cs[m][d] * inv;
        }
    }
}

// ---------------------------------------------------------------------------
// Kernel 4: fused maxsim.
// Block = (4 queries = 124 q-token rows, 1 doc). Grid (16, 256).
// GEMM 128x255x128 per block with fused rowwise max over j, then per-query
// segment sum / denom. 256 threads (16x16), micro-tile 8M x 4N, N tiled by 64.
// ~33.4 GFLOP fp32.
// ---------------------------------------------------------------------------
#define MS_SMEM_FLOATS (128*128 + 128*68 + 16*132 + 128)
#define MS_SMEM_BYTES  (MS_SMEM_FLOATS * 4)

__global__ void maxsim_kernel(float* __restrict__ out) {
    extern __shared__ float sm[];
    float* As     = sm;                    // [k=128][m=128]
    float* Bs     = As + 128 * 128;        // [k=128][n stride 68]
    float* red    = Bs + 128 * 68;         // [16][stride 132]
    float* rowmax = red + 16 * 132;        // [128]

    int t  = threadIdx.x;
    int qt = blockIdx.x;                   // query tile 0..15
    int c  = blockIdx.y;                   // doc 0..255
    int mg = t >> 4, ng = t & 15;
    int m0 = mg * 8, n0 = ng * 4;

    // Load A: rows qt*124 .. +123 of g_qcolT (contiguous per query), zero pad to 128.
    for (int idx = t; idx < 128 * 128; idx += 256) {
        int k = idx >> 7, m = idx & 127;
        float v = 0.f;
        if (m < 124) {
            int ql = m / 31, i = m - ql * 31;
            v = g_qcolT[(size_t)(qt * 4 + ql) * (D * QT) + k * QT + i];
        }
        As[idx] = v;
    }

    float rmax[8];
#pragma unroll
    for (int j = 0; j < 8; j++) rmax[j] = -INFINITY;
    __syncthreads();

    const float* cbase = g_ccolT + (size_t)c * (D * CT);

    for (int nt = 0; nt < 4; nt++) {
        int jbase = nt * 64;
        for (int idx = t; idx < 128 * 64; idx += 256) {
            int k = idx >> 6, n = idx & 63;
            int jg = jbase + n;
            Bs[k * 68 + n] = (jg < CT) ? cbase[k * CT + jg] : 0.f;
        }
        __syncthreads();

        float acc[8][4];
#pragma unroll
        for (int j = 0; j < 8; j++)
#pragma unroll
            for (int jj = 0; jj < 4; jj++) acc[j][jj] = 0.f;

#pragma unroll 4
        for (int k = 0; k < 128; k++) {
            float a[8];
            *(float4*)&a[0] = *(const float4*)&As[k * 128 + m0];
            *(float4*)&a[4] = *(const float4*)&As[k * 128 + m0 + 4];
            float b[4];
            *(float4*)&b[0] = *(const float4*)&Bs[k * 68 + n0];
#pragma unroll
            for (int j = 0; j < 8; j++)
#pragma unroll
                for (int jj = 0; jj < 4; jj++)
                    acc[j][jj] = fmaf(a[j], b[jj], acc[j][jj]);
        }
#pragma unroll
        for (int j = 0; j < 8; j++)
#pragma unroll
            for (int jj = 0; jj < 4; jj++)
                if (jbase + n0 + jj < CT) rmax[j] = fmaxf(rmax[j], acc[j][jj]);
        __syncthreads();
    }

    // Reduce the 16 n-groups' partial maxima per row.
#pragma unroll
    for (int j = 0; j < 8; j++) red[ng * 132 + m0 + j] = rmax[j];
    __syncthreads();
    if (t < 124) {
        float mx = red[t];
#pragma unroll
        for (int g = 1; g < 16; g++) mx = fmaxf(mx, red[g * 132 + t]);
        rowmax[t] = mx;
    }
    __syncthreads();
    if (t < 4) {
        int q = qt * 4 + t;
        float s = 0.f;
#pragma unroll
        for (int i = 0; i < 31; i++) s += rowmax[t * 31 + i];
        out[q * CC + c] = s / g_denom[q];
    }
}

// ---------------------------------------------------------------------------
extern "C" void kernel_launch(void* const* d_in, const int* in_sizes, int n_in,
                              void* d_out, int out_size) {
    const float* qh  = (const float*)d_in[0];
    const float* ch  = (const float*)d_in[1];
    const float* Wm  = (const float*)d_in[2];
    const float* bia = (const float*)d_in[3];
    const int*   qm  = (const int*)d_in[4];
    const int*   cm  = (const int*)d_in[5];
    float* out = (float*)d_out;

    // Idempotent attribute set (not a stream op; capture-safe, no allocation).
    cudaFuncSetAttribute(maxsim_kernel,
                         cudaFuncAttributeMaxDynamicSharedMemorySize,
                         MS_SMEM_BYTES);

    pooled_kernel<<<Q + CC, 256>>>(qh, ch, qm, cm, out);
    denom_kernel<<<1, 64>>>(qm);
    proj_kernel<<<NROWS / 32, 256>>>(qh, ch, Wm, bia, qm, cm);
    maxsim_kernel<<<dim3(16, 256), 256, MS_SMEM_BYTES>>>(out);
}

// round 2
// speedup vs baseline: 2.7953x; 2.7953x over previous
#include <cuda_runtime.h>
#include <math.h>
#include <stdint.h>

// Problem dims
#define Q    64
#define SQ   32
#define CC   256
#define SC   256
#define H    768
#define D    128
#define QT   31          // Sq-1 tokens per query
#define CT   255         // Sc-1 tokens per doc
#define QROWS (Q*QT)     // 1984
#define CROWS (CC*CT)    // 65280
#define NROWS (QROWS+CROWS) // 67264

// Scratch: projected+normalized token embeddings (tf32-rounded), ROW-MAJOR:
// rows [0,QROWS) are query tokens (q*31+i), rows [QROWS,NROWS) doc tokens (c*255+j).
__device__ float g_col[(size_t)NROWS * D];   // ~34.4 MB
__device__ float g_denom[Q];

// ---------------------------------------------------------------------------
// tf32 helpers
// ---------------------------------------------------------------------------
__device__ __forceinline__ float f2tf(float x) {
    uint32_t r;
    asm("cvt.rna.tf32.f32 %0, %1;" : "=r"(r) : "f"(x));
    return __uint_as_float(r);
}
__device__ __forceinline__ void mma_tf32(float* c, const uint32_t* a, const uint32_t* b) {
    asm volatile(
        "mma.sync.aligned.m16n8k8.row.col.f32.tf32.tf32.f32 "
        "{%0,%1,%2,%3},{%4,%5,%6,%7},{%8,%9},{%0,%1,%2,%3};\n"
        : "+f"(c[0]), "+f"(c[1]), "+f"(c[2]), "+f"(c[3])
        : "r"(a[0]), "r"(a[1]), "r"(a[2]), "r"(a[3]), "r"(b[0]), "r"(b[1]));
}

// ---------------------------------------------------------------------------
// Kernel 1: pooled vectors (fp32 exact). One block per row. 256 threads.
// ---------------------------------------------------------------------------
__global__ void pooled_kernel(const float* __restrict__ qh,
                              const float* __restrict__ ch,
                              const int*   __restrict__ qm,
                              const int*   __restrict__ cm,
                              float* __restrict__ out) {
    int r = blockIdx.x;
    const float* src;
    float mask;
    float* dst;
    if (r < Q) {
        src  = qh + (size_t)r * SQ * H;
        mask = (float)qm[r * SQ];
        dst  = out + Q * CC + (size_t)r * H;
    } else {
        int c = r - Q;
        src  = ch + (size_t)c * SC * H;
        mask = (float)cm[c * SC];
        dst  = out + Q * CC + Q * H + (size_t)c * H;
    }
    __shared__ float red[8];
    int t = threadIdx.x;
    float v[3];
    float s = 0.f;
#pragma unroll
    for (int it = 0; it < 3; it++) {
        float x = src[t + it * 256] * mask;
        v[it] = x;
        s += x * x;
    }
#pragma unroll
    for (int o = 16; o; o >>= 1) s += __shfl_xor_sync(0xffffffffu, s, o);
    if ((t & 31) == 0) red[t >> 5] = s;
    __syncthreads();
    if (t < 8) {
        float ss = red[t];
#pragma unroll
        for (int o = 4; o; o >>= 1) ss += __shfl_xor_sync(0xffu, ss, o);
        if (t == 0) red[0] = ss;
    }
    __syncthreads();
    float inv = 1.f / fmaxf(sqrtf(red[0]), 1e-12f);
#pragma unroll
    for (int it = 0; it < 3; it++) dst[t + it * 256] = v[it] * inv;
}

// ---------------------------------------------------------------------------
// Kernel 2: denominators
// ---------------------------------------------------------------------------
__global__ void denom_kernel(const int* __restrict__ qm) {
    int q = threadIdx.x;
    if (q < Q) {
        int s = 0;
        for (int i = 1; i < SQ; i++) s += qm[q * SQ + i];
        g_denom[q] = (float)s;
    }
}

// ---------------------------------------------------------------------------
// Kernel 3: projection + l2norm via tf32 tensor cores.
// Block: 64 rows x 128 cols (full D). 8 warps = 2(M) x 4(N), warp tile 32x32.
// mma m16n8k8, K tiled by 32 (24 iters). Output row-major tf32-rounded.
// ---------------------------------------------------------------------------
#define P_SA 36
#define P_SW 132
__global__ __launch_bounds__(256) void proj_kernel(const float* __restrict__ qh,
                                                   const float* __restrict__ ch,
                                                   const float* __restrict__ Wm,
                                                   const float* __restrict__ bias,
                                                   const int*   __restrict__ qm,
                                                   const int*   __restrict__ cm) {
    __shared__ float As[64 * P_SA];          // [m][k] tf32
    __shared__ float Ws[32 * P_SW];          // [k][d] tf32
    __shared__ float rowsq[64][4];
    __shared__ float invn[64];
    __shared__ const float* srcp[64];
    __shared__ float mk[64];

    int t = threadIdx.x;
    int w = t >> 5, lane = t & 31, g = lane >> 2, tg = lane & 3;
    int mw = w & 1, nw = w >> 1;
    int m_warp = mw * 32, n_warp = nw * 32;

    if (t < 64) {
        int r = blockIdx.x * 64 + t;
        if (r < QROWS) {
            int q = r / QT, i = r - q * QT;
            srcp[t] = qh + (size_t)(q * SQ + i + 1) * H;
            mk[t]   = (float)qm[q * SQ + i + 1];
        } else {
            int rc = r - QROWS;
            int c = rc / CT, j = rc - c * CT;
            srcp[t] = ch + (size_t)(c * SC + j + 1) * H;
            mk[t]   = (float)cm[c * SC + j + 1];
        }
    }

    // Accumulators, bias-initialized (fp32 exact).
    float acc[2][4][4];
#pragma unroll
    for (int nt4 = 0; nt4 < 4; nt4++) {
        int col = n_warp + nt4 * 8 + 2 * tg;
        float b0 = bias[col], b1 = bias[col + 1];
#pragma unroll
        for (int mt = 0; mt < 2; mt++) {
            acc[mt][nt4][0] = b0; acc[mt][nt4][1] = b1;
            acc[mt][nt4][2] = b0; acc[mt][nt4][3] = b1;
        }
    }
    __syncthreads();

    for (int kt = 0; kt < H; kt += 32) {
        __syncthreads();
        // A tile: 64 rows x 32 k (masked, tf32). 512 float4 -> 2 per thread.
#pragma unroll
        for (int it = 0; it < 2; it++) {
            int idx = t + it * 256;
            int m = idx >> 3, k4 = idx & 7;
            float4 a = *(const float4*)(srcp[m] + kt + k4 * 4);
            float mm = mk[m];
            float* d = &As[m * P_SA + k4 * 4];
            d[0] = f2tf(a.x * mm); d[1] = f2tf(a.y * mm);
            d[2] = f2tf(a.z * mm); d[3] = f2tf(a.w * mm);
        }
        // W tile: 32 k x 128 d (tf32). 1024 float4 -> 4 per thread.
#pragma unroll
        for (int it = 0; it < 4; it++) {
            int idx = t + it * 256;
            int k = idx >> 5, d4 = idx & 31;
            float4 wv = *(const float4*)(Wm + (size_t)(kt + k) * D + d4 * 4);
            float* d = &Ws[k * P_SW + d4 * 4];
            d[0] = f2tf(wv.x); d[1] = f2tf(wv.y);
            d[2] = f2tf(wv.z); d[3] = f2tf(wv.w);
        }
        __syncthreads();
#pragma unroll
        for (int ks = 0; ks < 4; ks++) {
            int k0 = ks * 8;
            uint32_t afr[2][4], bfr[4][2];
#pragma unroll
            for (int mt = 0; mt < 2; mt++) {
                int base = m_warp + mt * 16;
                afr[mt][0] = __float_as_uint(As[(base + g)     * P_SA + k0 + tg]);
                afr[mt][1] = __float_as_uint(As[(base + g + 8) * P_SA + k0 + tg]);
                afr[mt][2] = __float_as_uint(As[(base + g)     * P_SA + k0 + tg + 4]);
                afr[mt][3] = __float_as_uint(As[(base + g + 8) * P_SA + k0 + tg + 4]);
            }
#pragma unroll
            for (int nt4 = 0; nt4 < 4; nt4++) {
                int col = n_warp + nt4 * 8 + g;
                bfr[nt4][0] = __float_as_uint(Ws[(k0 + tg)     * P_SW + col]);
                bfr[nt4][1] = __float_as_uint(Ws[(k0 + tg + 4) * P_SW + col]);
            }
#pragma unroll
            for (int mt = 0; mt < 2; mt++)
#pragma unroll
                for (int nt4 = 0; nt4 < 4; nt4++)
                    mma_tf32(acc[mt][nt4], afr[mt], bfr[nt4]);
        }
    }

    // Epilogue: per-row sum of squares (warp covers 32 of 128 cols).
    float pr[2][2];
#pragma unroll
    for (int mt = 0; mt < 2; mt++)
#pragma unroll
        for (int h = 0; h < 2; h++) {
            float s = 0.f;
#pragma unroll
            for (int nt4 = 0; nt4 < 4; nt4++) {
                float c0 = acc[mt][nt4][2 * h], c1 = acc[mt][nt4][2 * h + 1];
                s += c0 * c0 + c1 * c1;
            }
            pr[mt][h] = s;
        }
#pragma unroll
    for (int off = 1; off <= 2; off <<= 1) {
#pragma unroll
        for (int mt = 0; mt < 2; mt++)
#pragma unroll
            for (int h = 0; h < 2; h++)
                pr[mt][h] += __shfl_xor_sync(0xffffffffu, pr[mt][h], off);
    }
    if (tg == 0) {
#pragma unroll
        for (int mt = 0; mt < 2; mt++)
#pragma unroll
            for (int h = 0; h < 2; h++)
                rowsq[m_warp + mt * 16 + g + 8 * h][nw] = pr[mt][h];
    }
    __syncthreads();
    if (t < 64) {
        float s = rowsq[t][0] + rowsq[t][1] + rowsq[t][2] + rowsq[t][3];
        invn[t] = 1.f / fmaxf(sqrtf(s), 1e-12f);
    }
    __syncthreads();

    size_t gbase = (size_t)blockIdx.x * 64;
#pragma unroll
    for (int mt = 0; mt < 2; mt++)
#pragma unroll
        for (int h = 0; h < 2; h++) {
            int r = m_warp + mt * 16 + g + 8 * h;
            float inv = invn[r];
            float* dst = g_col + (gbase + r) * D;
#pragma unroll
            for (int nt4 = 0; nt4 < 4; nt4++) {
                int col = n_warp + nt4 * 8 + 2 * tg;
                float2 v;
                v.x = f2tf(acc[mt][nt4][2 * h]     * inv);
                v.y = f2tf(acc[mt][nt4][2 * h + 1] * inv);
                *(float2*)(dst + col) = v;
            }
        }
}

// ---------------------------------------------------------------------------
// Kernel 4: fused maxsim via tf32 tensor cores.
// Block = (4 queries = 124 rows pad 128) x (1 doc). Grid (16, 256).
// 8 warps = 4(M) x 2(N), warp tile 32x32; N tiled by 64 (4 tiles), K=128.
// Both operands in [row][k] smem layout (conflict-free frag reads, no
// transpose on store). Fused col-guarded row-max epilogue.
// ---------------------------------------------------------------------------
#define MS_SA 132
#define MS_SB 132
#define MS_SMEM_FLOATS (128*MS_SA + 64*MS_SB + 2*128 + 128)
#define MS_SMEM_BYTES  (MS_SMEM_FLOATS * 4)

__global__ __launch_bounds__(256) void maxsim_kernel(float* __restrict__ out) {
    extern __shared__ float sm[];
    float* As     = sm;                      // [m=128][k] stride 132
    float* Bs     = As + 128 * MS_SA;        // [n=64][k] stride 132
    float* red    = Bs + 64 * MS_SB;         // [2][128]
    float* rowmax = red + 2 * 128;           // [128]

    int t = threadIdx.x;
    int w = t >> 5, lane = t & 31, g = lane >> 2, tg = lane & 3;
    int mw = w & 3, nw = w >> 2;
    int m_warp = mw * 32, n_warp = nw * 32;

    int qt = blockIdx.x;                     // query tile 0..15
    int c  = blockIdx.y;                     // doc 0..255

    // Load A once: 124 contiguous rows of g_col starting at qt*124, pad to 128.
    const float* abase = g_col + (size_t)qt * 124 * D;
#pragma unroll
    for (int it = 0; it < 16; it++) {
        int idx = t + it * 256;
        int m = idx >> 5, k4 = idx & 31;
        float4 v = make_float4(0.f, 0.f, 0.f, 0.f);
        if (m < 124) v = *(const float4*)(abase + (size_t)m * D + k4 * 4);
        *(float4*)&As[m * MS_SA + k4 * 4] = v;
    }

    float rmax[4];
#pragma unroll
    for (int s = 0; s < 4; s++) rmax[s] = -INFINITY;

    const float* bbase = g_col + (size_t)(QROWS + c * CT) * D;

    for (int nt = 0; nt < 4; nt++) {
        __syncthreads();                     // As ready / Bs consumers done
        // B tile: 64 rows (j = nt*64+n), full K=128. 2048 float4 -> 8 per thread.
#pragma unroll
        for (int it = 0; it < 8; it++) {
            int idx = t + it * 256;
            int n = idx >> 5, k4 = idx & 31;
            int j = nt * 64 + n;
            float4 v = make_float4(0.f, 0.f, 0.f, 0.f);
            if (j < CT) v = *(const float4*)(bbase + (size_t)j * D + k4 * 4);
            *(float4*)&Bs[n * MS_SB + k4 * 4] = v;
        }
        __syncthreads();

        float acc[2][4][4];
#pragma unroll
        for (int mt = 0; mt < 2; mt++)
#pragma unroll
            for (int nt4 = 0; nt4 < 4; nt4++)
#pragma unroll
                for (int i = 0; i < 4; i++) acc[mt][nt4][i] = 0.f;

#pragma unroll
        for (int ks = 0; ks < 16; ks++) {
            int k0 = ks * 8;
            uint32_t afr[2][4], bfr[4][2];
#pragma unroll
            for (int mt = 0; mt < 2; mt++) {
                int base = m_warp + mt * 16;
                afr[mt][0] = __float_as_uint(As[(base + g)     * MS_SA + k0 + tg]);
                afr[mt][1] = __float_as_uint(As[(base + g + 8) * MS_SA + k0 + tg]);
                afr[mt][2] = __float_as_uint(As[(base + g)     * MS_SA + k0 + tg + 4]);
                afr[mt][3] = __float_as_uint(As[(base + g + 8) * MS_SA + k0 + tg + 4]);
            }
#pragma unroll
            for (int nt4 = 0; nt4 < 4; nt4++) {
                int n = n_warp + nt4 * 8 + g;
                bfr[nt4][0] = __float_as_uint(Bs[n * MS_SB + k0 + tg]);
                bfr[nt4][1] = __float_as_uint(Bs[n * MS_SB + k0 + tg + 4]);
            }
#pragma unroll
            for (int mt = 0; mt < 2; mt++)
#pragma unroll
                for (int nt4 = 0; nt4 < 4; nt4++)
                    mma_tf32(acc[mt][nt4], afr[mt], bfr[nt4]);
        }

        // Fused row-max update (guard padded j columns).
#pragma unroll
        for (int mt = 0; mt < 2; mt++)
#pragma unroll
            for (int nt4 = 0; nt4 < 4; nt4++)
#pragma unroll
                for (int i = 0; i < 4; i++) {
                    int j = nt * 64 + n_warp + nt4 * 8 + 2 * tg + (i & 1);
                    if (j < CT) {
                        int s = mt * 2 + (i >> 1);
                        rmax[s] = fmaxf(rmax[s], acc[mt][nt4][i]);
                    }
                }
    }

    // Reduce over tg lanes (share rows), then across the 2 n-warps.
#pragma unroll
    for (int off = 1; off <= 2; off <<= 1)
#pragma unroll
        for (int s = 0; s < 4; s++)
            rmax[s] = fmaxf(rmax[s], __shfl_xor_sync(0xffffffffu, rmax[s], off));
    if (tg == 0) {
#pragma unroll
        for (int mt = 0; mt < 2; mt++)
#pragma unroll
            for (int h = 0; h < 2; h++)
                red[nw * 128 + m_warp + mt * 16 + g + 8 * h] = rmax[mt * 2 + h];
    }
    __syncthreads();
    if (t < 124) rowmax[t] = fmaxf(red[t], red[128 + t]);
    __syncthreads();
    if (t < 4) {
        int q = qt * 4 + t;
        float s = 0.f;
#pragma unroll
        for (int i = 0; i < 31; i++) s += rowmax[t * 31 + i];
        out[q * CC + c] = s / g_denom[q];
    }
}

// ---------------------------------------------------------------------------
extern "C" void kernel_launch(void* const* d_in, const int* in_sizes, int n_in,
                              void* d_out, int out_size) {
    const float* qh  = (const float*)d_in[0];
    const float* ch  = (const float*)d_in[1];
    const float* Wm  = (const float*)d_in[2];
    const float* bia = (const float*)d_in[3];
    const int*   qm  = (const int*)d_in[4];
    const int*   cm  = (const int*)d_in[5];
    float* out = (float*)d_out;

    cudaFuncSetAttribute(maxsim_kernel,
                         cudaFuncAttributeMaxDynamicSharedMemorySize,
                         MS_SMEM_BYTES);

    pooled_kernel<<<Q + CC, 256>>>(qh, ch, qm, cm, out);
    denom_kernel<<<1, 64>>>(qm);
    proj_kernel<<<NROWS / 64, 256>>>(qh, ch, Wm, bia, qm, cm);
    maxsim_kernel<<<dim3(16, 256), 256, MS_SMEM_BYTES>>>(out);
}

// round 4
// speedup vs baseline: 4.6132x; 1.6503x over previous
#include <cuda_runtime.h>
#include <math.h>
#include <stdint.h>

// Problem dims
#define Q    64
#define SQ   32
#define CC   256
#define SC   256
#define H    768
#define D    128
#define QT   31
#define CT   255
#define QROWS (Q*QT)     // 1984
#define CROWS (CC*CT)    // 65280
#define NROWS (QROWS+CROWS)

// Scratch: projected+normalized token embeddings (tf32-rounded), ROW-MAJOR.
__device__ float g_col[(size_t)NROWS * D];
__device__ float g_denom[Q];

// ---------------------------------------------------------------------------
// helpers
// ---------------------------------------------------------------------------
__device__ __forceinline__ float f2tf(float x) {
    uint32_t r;
    asm("cvt.rna.tf32.f32 %0, %1;" : "=r"(r) : "f"(x));
    return __uint_as_float(r);
}
__device__ __forceinline__ void mma_tf32(float* c, const uint32_t* a, const uint32_t* b) {
    asm volatile(
        "mma.sync.aligned.m16n8k8.row.col.f32.tf32.tf32.f32 "
        "{%0,%1,%2,%3},{%4,%5,%6,%7},{%8,%9},{%0,%1,%2,%3};\n"
        : "+f"(c[0]), "+f"(c[1]), "+f"(c[2]), "+f"(c[3])
        : "r"(a[0]), "r"(a[1]), "r"(a[2]), "r"(a[3]), "r"(b[0]), "r"(b[1]));
}
__device__ __forceinline__ uint32_t smem_u32(const void* p) {
    uint32_t a;
    asm("{ .reg .u64 t; cvta.to.shared.u64 t, %1; cvt.u32.u64 %0, t; }" : "=r"(a) : "l"(p));
    return a;
}
#define CP_ASYNC16(dst_u32, src_ptr) \
    asm volatile("cp.async.ca.shared.global [%0], [%1], 16;" :: "r"(dst_u32), "l"(src_ptr))
#define CP_COMMIT() asm volatile("cp.async.commit_group;" ::: "memory")
#define CP_WAIT1()  asm volatile("cp.async.wait_group 1;" ::: "memory")
#define CP_WAIT0()  asm volatile("cp.async.wait_group 0;" ::: "memory")

// ---------------------------------------------------------------------------
// Kernel 1: pooled vectors (fp32 exact)
// ---------------------------------------------------------------------------
__global__ void pooled_kernel(const float* __restrict__ qh,
                              const float* __restrict__ ch,
                              const int*   __restrict__ qm,
                              const int*   __restrict__ cm,
                              float* __restrict__ out) {
    int r = blockIdx.x;
    const float* src;
    float mask;
    float* dst;
    if (r < Q) {
        src  = qh + (size_t)r * SQ * H;
        mask = (float)qm[r * SQ];
        dst  = out + Q * CC + (size_t)r * H;
    } else {
        int c = r - Q;
        src  = ch + (size_t)c * SC * H;
        mask = (float)cm[c * SC];
        dst  = out + Q * CC + Q * H + (size_t)c * H;
    }
    __shared__ float red[8];
    int t = threadIdx.x;
    float v[3];
    float s = 0.f;
#pragma unroll
    for (int it = 0; it < 3; it++) {
        float x = src[t + it * 256] * mask;
        v[it] = x;
        s += x * x;
    }
#pragma unroll
    for (int o = 16; o; o >>= 1) s += __shfl_xor_sync(0xffffffffu, s, o);
    if ((t & 31) == 0) red[t >> 5] = s;
    __syncthreads();
    if (t < 8) {
        float ss = red[t];
#pragma unroll
        for (int o = 4; o; o >>= 1) ss += __shfl_xor_sync(0xffu, ss, o);
        if (t == 0) red[0] = ss;
    }
    __syncthreads();
    float inv = 1.f / fmaxf(sqrtf(red[0]), 1e-12f);
#pragma unroll
    for (int it = 0; it < 3; it++) dst[t + it * 256] = v[it] * inv;
}

// ---------------------------------------------------------------------------
// Kernel 2: denominators
// ---------------------------------------------------------------------------
__global__ void denom_kernel(const int* __restrict__ qm) {
    int q = threadIdx.x;
    if (q < Q) {
        int s = 0;
        for (int i = 1; i < SQ; i++) s += qm[q * SQ + i];
        g_denom[q] = (float)s;
    }
}

// ---------------------------------------------------------------------------
// Kernel 3: projection + l2norm, tf32 mma.sync with cp.async double buffering.
// Block: 64 rows x 128 cols. 8 warps = 2(M) x 4(N), warp tile 32x32.
// K tiled by 32, pipeline depth 2. Mask+bias applied POST-GEMM:
//   col = l2norm( mask*(h@W) + b )   (mask in {0,1} => identical to ref)
// ---------------------------------------------------------------------------
#define P_SA 36      // A row stride (32 k + pad 4)
#define P_SW 132     // W row stride (128 d + pad 4)
__global__ __launch_bounds__(256) void proj_kernel(const float* __restrict__ qh,
                                                   const float* __restrict__ ch,
                                                   const float* __restrict__ Wm,
                                                   const float* __restrict__ bias,
                                                   const int*   __restrict__ qm,
                                                   const int*   __restrict__ cm) {
    __shared__ float As[2][64 * P_SA];
    __shared__ float Ws[2][32 * P_SW];
    __shared__ float rowsq[64][4];
    __shared__ float invn[64];
    __shared__ const float* srcp[64];
    __shared__ float mk[64];

    int t = threadIdx.x;
    int w = t >> 5, lane = t & 31, g = lane >> 2, tg = lane & 3;
    int mw = w & 1, nw = w >> 1;
    int m_warp = mw * 32, n_warp = nw * 32;

    if (t < 64) {
        int r = blockIdx.x * 64 + t;
        if (r < QROWS) {
            int q = r / QT, i = r - q * QT;
            srcp[t] = qh + (size_t)(q * SQ + i + 1) * H;
            mk[t]   = (float)qm[q * SQ + i + 1];
        } else {
            int rc = r - QROWS;
            int c = rc / CT, j = rc - c * CT;
            srcp[t] = ch + (size_t)(c * SC + j + 1) * H;
            mk[t]   = (float)cm[c * SC + j + 1];
        }
    }

    // bias regs for this thread's output columns
    float binit[4][2];
#pragma unroll
    for (int nt4 = 0; nt4 < 4; nt4++) {
        int col = n_warp + nt4 * 8 + 2 * tg;
        binit[nt4][0] = bias[col];
        binit[nt4][1] = bias[col + 1];
    }
    __syncthreads();   // srcp/mk visible to all

    // Stage tile (buf, kt) via cp.async: A 2 chunks, W 4 chunks per thread.
    uint32_t sA0 = smem_u32(&As[0][0]), sA1 = smem_u32(&As[1][0]);
    uint32_t sW0 = smem_u32(&Ws[0][0]), sW1 = smem_u32(&Ws[1][0]);
    int aM = t >> 3, aK4 = t & 7;          // A chunk 0: m=t>>3 covers rows 0..31
    // chunk layout: idx = t + it*256 -> m = idx>>3, k4 = idx&7

#define STAGE(bufA, bufW, KT) do {                                              \
    _Pragma("unroll")                                                           \
    for (int itc = 0; itc < 2; itc++) {                                         \
        int idx = t + itc * 256;                                                \
        int m = idx >> 3, k4 = idx & 7;                                         \
        CP_ASYNC16((bufA) + (m * P_SA + k4 * 4) * 4, srcp[m] + (KT) + k4 * 4);  \
    }                                                                           \
    _Pragma("unroll")                                                           \
    for (int itc = 0; itc < 4; itc++) {                                         \
        int idx = t + itc * 256;                                                \
        int k = idx >> 5, d4 = idx & 31;                                        \
        CP_ASYNC16((bufW) + (k * P_SW + d4 * 4) * 4,                            \
                   Wm + (size_t)((KT) + k) * D + d4 * 4);                       \
    }                                                                           \
} while (0)

    STAGE(sA0, sW0, 0);
    CP_COMMIT();

    float acc[2][4][4];
#pragma unroll
    for (int mt = 0; mt < 2; mt++)
#pragma unroll
        for (int nt4 = 0; nt4 < 4; nt4++)
#pragma unroll
            for (int i = 0; i < 4; i++) acc[mt][nt4][i] = 0.f;

    for (int it = 0; it < 24; it++) {
        if (it < 23) {
            if (it & 1) STAGE(sA0, sW0, (it + 1) * 32);
            else        STAGE(sA1, sW1, (it + 1) * 32);
            CP_COMMIT();
            CP_WAIT1();
        } else {
            CP_WAIT0();
        }
        __syncthreads();
        const float* A = As[it & 1];
        const float* W = Ws[it & 1];
#pragma unroll
        for (int ks = 0; ks < 4; ks++) {
            int k0 = ks * 8;
            uint32_t afr[2][4], bfr[4][2];
#pragma unroll
            for (int mt = 0; mt < 2; mt++) {
                int base = m_warp + mt * 16;
                afr[mt][0] = __float_as_uint(A[(base + g)     * P_SA + k0 + tg]);
                afr[mt][1] = __float_as_uint(A[(base + g + 8) * P_SA + k0 + tg]);
                afr[mt][2] = __float_as_uint(A[(base + g)     * P_SA + k0 + tg + 4]);
                afr[mt][3] = __float_as_uint(A[(base + g + 8) * P_SA + k0 + tg + 4]);
            }
#pragma unroll
            for (int nt4 = 0; nt4 < 4; nt4++) {
                int col = n_warp + nt4 * 8 + g;
                bfr[nt4][0] = __float_as_uint(W[(k0 + tg)     * P_SW + col]);
                bfr[nt4][1] = __float_as_uint(W[(k0 + tg + 4) * P_SW + col]);
            }
#pragma unroll
            for (int mt = 0; mt < 2; mt++)
#pragma unroll
                for (int nt4 = 0; nt4 < 4; nt4++)
                    mma_tf32(acc[mt][nt4], afr[mt], bfr[nt4]);
        }
        __syncthreads();
    }

    // Apply mask + bias post-GEMM.
    float mrow[2][2];
#pragma unroll
    for (int mt = 0; mt < 2; mt++) {
        mrow[mt][0] = mk[m_warp + mt * 16 + g];
        mrow[mt][1] = mk[m_warp + mt * 16 + g + 8];
    }
#pragma unroll
    for (int mt = 0; mt < 2; mt++)
#pragma unroll
        for (int nt4 = 0; nt4 < 4; nt4++)
#pragma unroll
            for (int i = 0; i < 4; i++)
                acc[mt][nt4][i] = mrow[mt][i >> 1] * acc[mt][nt4][i] + binit[nt4][i & 1];

    // Row-wise sum of squares -> l2 norm.
    float pr[2][2];
#pragma unroll
    for (int mt = 0; mt < 2; mt++)
#pragma unroll
        for (int h = 0; h < 2; h++) {
            float s = 0.f;
#pragma unroll
            for (int nt4 = 0; nt4 < 4; nt4++) {
                float c0 = acc[mt][nt4][2 * h], c1 = acc[mt][nt4][2 * h + 1];
                s += c0 * c0 + c1 * c1;
            }
            pr[mt][h] = s;
        }
#pragma unroll
    for (int off = 1; off <= 2; off <<= 1) {
#pragma unroll
        for (int mt = 0; mt < 2; mt++)
#pragma unroll
            for (int h = 0; h < 2; h++)
                pr[mt][h] += __shfl_xor_sync(0xffffffffu, pr[mt][h], off);
    }
    if (tg == 0) {
#pragma unroll
        for (int mt = 0; mt < 2; mt++)
#pragma unroll
            for (int h = 0; h < 2; h++)
                rowsq[m_warp + mt * 16 + g + 8 * h][nw] = pr[mt][h];
    }
    __syncthreads();
    if (t < 64) {
        float s = rowsq[t][0] + rowsq[t][1] + rowsq[t][2] + rowsq[t][3];
        invn[t] = 1.f / fmaxf(sqrtf(s), 1e-12f);
    }
    __syncthreads();

    size_t gbase = (size_t)blockIdx.x * 64;
#pragma unroll
    for (int mt = 0; mt < 2; mt++)
#pragma unroll
        for (int h = 0; h < 2; h++) {
            int r = m_warp + mt * 16 + g + 8 * h;
            float inv = invn[r];
            float* dst = g_col + (gbase + r) * D;
#pragma unroll
            for (int nt4 = 0; nt4 < 4; nt4++) {
                int col = n_warp + nt4 * 8 + 2 * tg;
                float2 v;
                v.x = f2tf(acc[mt][nt4][2 * h]     * inv);
                v.y = f2tf(acc[mt][nt4][2 * h + 1] * inv);
                *(float2*)(dst + col) = v;
            }
        }
#undef STAGE
}

// ---------------------------------------------------------------------------
// Kernel 4: fused maxsim, tf32 mma.sync, FULL-DOC smem residency.
// Block = (4 queries, 128 rows) x (1 doc, 256 rows padded). Grid (16, 256).
// 8 warps = 2(M) x 4(N), warp tile 64x64 (Mt=4, Nt=8), acc 128 regs.
// Single K pass (16 k-slices); A-frags read ONCE per pass (words/mma = 1.0,
// vs 2.0 in the round-2 kernel -> 4x less fragment crossbar traffic).
// Fused row-max epilogue with j<255 guard.
// smem: A 128x132 + B 256x132 + red = 205312 B -> 1 CTA/SM.
// ---------------------------------------------------------------------------
#define MS_SA 132
#define MS_SB 132
#define MS_SMEM_FLOATS (128*MS_SA + 256*MS_SB + 4*128 + 128)
#define MS_SMEM_BYTES  (MS_SMEM_FLOATS * 4)

__global__ __launch_bounds__(256, 1) void maxsim_kernel(float* __restrict__ out) {
    extern __shared__ float sm[];
    float* As     = sm;                      // [m=128][k] stride 132
    float* Bs     = As + 128 * MS_SA;        // [n=256][k] stride 132
    float* red    = Bs + 256 * MS_SB;        // [4][128]
    float* rowmax = red + 4 * 128;           // [128]

    int t = threadIdx.x;
    int w = t >> 5, lane = t & 31, g = lane >> 2, tg = lane & 3;
    int mw = w & 1, nw = w >> 1;             // 2 M-groups, 4 N-groups
    int m_warp = mw * 64, n_warp = nw * 64;

    int qt = blockIdx.x;                     // query tile 0..15
    int c  = blockIdx.y;                     // doc 0..255

    // Load A: 124 rows (pad to 128 with zeros), 128 k.
    const float* abase = g_col + (size_t)qt * 124 * D;
#pragma unroll
    for (int it = 0; it < 16; it++) {
        int idx = t + it * 256;
        int m = idx >> 5, k4 = idx & 31;
        float4 v = make_float4(0.f, 0.f, 0.f, 0.f);
        if (m < 124) v = *(const float4*)(abase + (size_t)m * D + k4 * 4);
        *(float4*)&As[m * MS_SA + k4 * 4] = v;
    }
    // Load B: whole doc, 255 rows (pad to 256), 128 k.
    const float* bbase = g_col + (size_t)(QROWS + c * CT) * D;
#pragma unroll
    for (int it = 0; it < 32; it++) {
        int idx = t + it * 256;
        int n = idx >> 5, k4 = idx & 31;
        float4 v = make_float4(0.f, 0.f, 0.f, 0.f);
        if (n < CT) v = *(const float4*)(bbase + (size_t)n * D + k4 * 4);
        *(float4*)&Bs[n * MS_SB + k4 * 4] = v;
    }
    __syncthreads();

    float acc[4][8][4];
#pragma unroll
    for (int mt = 0; mt < 4; mt++)
#pragma unroll
        for (int nt = 0; nt < 8; nt++)
#pragma unroll
            for (int i = 0; i < 4; i++) acc[mt][nt][i] = 0.f;

#pragma unroll 2
    for (int ks = 0; ks < 16; ks++) {
        int k0 = ks * 8;
        uint32_t afr[4][4], bfr[8][2];
#pragma unroll
        for (int mt = 0; mt < 4; mt++) {
            int base = m_warp + mt * 16;
            afr[mt][0] = __float_as_uint(As[(base + g)     * MS_SA + k0 + tg]);
            afr[mt][1] = __float_as_uint(As[(base + g + 8) * MS_SA + k0 + tg]);
            afr[mt][2] = __float_as_uint(As[(base + g)     * MS_SA + k0 + tg + 4]);
            afr[mt][3] = __float_as_uint(As[(base + g + 8) * MS_SA + k0 + tg + 4]);
        }
#pragma unroll
        for (int nt = 0; nt < 8; nt++) {
            int n = n_warp + nt * 8 + g;
            bfr[nt][0] = __float_as_uint(Bs[n * MS_SB + k0 + tg]);
            bfr[nt][1] = __float_as_uint(Bs[n * MS_SB + k0 + tg + 4]);
        }
#pragma unroll
        for (int mt = 0; mt < 4; mt++)
#pragma unroll
            for (int nt = 0; nt < 8; nt++)
                mma_tf32(acc[mt][nt], afr[mt], bfr[nt]);
    }

    // Fused row-max (guard padded col j=255).
    float rp[4][2];
#pragma unroll
    for (int mt = 0; mt < 4; mt++) { rp[mt][0] = -INFINITY; rp[mt][1] = -INFINITY; }
#pragma unroll
    for (int mt = 0; mt < 4; mt++)
#pragma unroll
        for (int nt = 0; nt < 8; nt++)
#pragma unroll
            for (int i = 0; i < 4; i++) {
                int j = n_warp + nt * 8 + 2 * tg + (i & 1);
                if (j < CT) rp[mt][i >> 1] = fmaxf(rp[mt][i >> 1], acc[mt][nt][i]);
            }
#pragma unroll
    for (int off = 1; off <= 2; off <<= 1)
#pragma unroll
        for (int mt = 0; mt < 4; mt++)
#pragma unroll
            for (int h = 0; h < 2; h++)
                rp[mt][h] = fmaxf(rp[mt][h], __shfl_xor_sync(0xffffffffu, rp[mt][h], off));
    if (tg == 0) {
#pragma unroll
        for (int mt = 0; mt < 4; mt++)
#pragma unroll
            for (int h = 0; h < 2; h++)
                red[nw * 128 + m_warp + mt * 16 + g + 8 * h] = rp[mt][h];
    }
    __syncthreads();
    if (t < 128) {
        float mx = fmaxf(fmaxf(red[t], red[128 + t]), fmaxf(red[256 + t], red[384 + t]));
        rowmax[t] = mx;
    }
    __syncthreads();
    if (t < 4) {
        int q = qt * 4 + t;
        float s = 0.f;
#pragma unroll
        for (int i = 0; i < 31; i++) s += rowmax[t * 31 + i];
        out[q * CC + c] = s / g_denom[q];
    }
}

// ---------------------------------------------------------------------------
extern "C" void kernel_launch(void* const* d_in, const int* in_sizes, int n_in,
                              void* d_out, int out_size) {
    const float* qh  = (const float*)d_in[0];
    const float* ch  = (const float*)d_in[1];
    const float* Wm  = (const float*)d_in[2];
    const float* bia = (const float*)d_in[3];
    const int*   qm  = (const int*)d_in[4];
    const int*   cm  = (const int*)d_in[5];
    float* out = (float*)d_out;

    cudaFuncSetAttribute(maxsim_kernel,
                         cudaFuncAttributeMaxDynamicSharedMemorySize,
                         MS_SMEM_BYTES);

    pooled_kernel<<<Q + CC, 256>>>(qh, ch, qm, cm, out);
    denom_kernel<<<1, 64>>>(qm);
    proj_kernel<<<NROWS / 64, 256>>>(qh, ch, Wm, bia, qm, cm);
    maxsim_kernel<<<dim3(16, 256), 256, MS_SMEM_BYTES>>>(out);
}

// round 5
// speedup vs baseline: 5.1237x; 1.1107x over previous
#include <cuda_runtime.h>
#include <math.h>
#include <stdint.h>

// Problem dims
#define Q    64
#define SQ   32
#define CC   256
#define SC   256
#define H    768
#define D    128
#define QT   31
#define CT   255
#define QROWS (Q*QT)     // 1984
#define CROWS (CC*CT)    // 65280
#define NROWS (QROWS+CROWS)

// Scratch: projected+normalized token embeddings (tf32-rounded), ROW-MAJOR.
__device__ float g_col[(size_t)NROWS * D];
__device__ float g_denom[Q];

// ---------------------------------------------------------------------------
// helpers
// ---------------------------------------------------------------------------
__device__ __forceinline__ float f2tf(float x) {
    uint32_t r;
    asm("cvt.rna.tf32.f32 %0, %1;" : "=r"(r) : "f"(x));
    return __uint_as_float(r);
}
__device__ __forceinline__ void mma_tf32(float* c, const uint32_t* a, const uint32_t* b) {
    asm volatile(
        "mma.sync.aligned.m16n8k8.row.col.f32.tf32.tf32.f32 "
        "{%0,%1,%2,%3},{%4,%5,%6,%7},{%8,%9},{%0,%1,%2,%3};\n"
        : "+f"(c[0]), "+f"(c[1]), "+f"(c[2]), "+f"(c[3])
        : "r"(a[0]), "r"(a[1]), "r"(a[2]), "r"(a[3]), "r"(b[0]), "r"(b[1]));
}
__device__ __forceinline__ uint32_t smem_u32(const void* p) {
    uint32_t a;
    asm("{ .reg .u64 t; cvta.to.shared.u64 t, %1; cvt.u32.u64 %0, t; }" : "=r"(a) : "l"(p));
    return a;
}
#define CP_ASYNC16(dst_u32, src_ptr) \
    asm volatile("cp.async.ca.shared.global [%0], [%1], 16;" :: "r"(dst_u32), "l"(src_ptr))
#define CP_COMMIT() asm volatile("cp.async.commit_group;" ::: "memory")
#define CP_WAIT1()  asm volatile("cp.async.wait_group 1;" ::: "memory")
#define CP_WAIT0()  asm volatile("cp.async.wait_group 0;" ::: "memory")

// ---------------------------------------------------------------------------
// Kernel 1: pooled vectors (fp32 exact)
// ---------------------------------------------------------------------------
__global__ void pooled_kernel(const float* __restrict__ qh,
                              const float* __restrict__ ch,
                              const int*   __restrict__ qm,
                              const int*   __restrict__ cm,
                              float* __restrict__ out) {
    int r = blockIdx.x;
    const float* src;
    float mask;
    float* dst;
    if (r < Q) {
        src  = qh + (size_t)r * SQ * H;
        mask = (float)qm[r * SQ];
        dst  = out + Q * CC + (size_t)r * H;
    } else {
        int c = r - Q;
        src  = ch + (size_t)c * SC * H;
        mask = (float)cm[c * SC];
        dst  = out + Q * CC + Q * H + (size_t)c * H;
    }
    __shared__ float red[8];
    int t = threadIdx.x;
    float v[3];
    float s = 0.f;
#pragma unroll
    for (int it = 0; it < 3; it++) {
        float x = src[t + it * 256] * mask;
        v[it] = x;
        s += x * x;
    }
#pragma unroll
    for (int o = 16; o; o >>= 1) s += __shfl_xor_sync(0xffffffffu, s, o);
    if ((t & 31) == 0) red[t >> 5] = s;
    __syncthreads();
    if (t < 8) {
        float ss = red[t];
#pragma unroll
        for (int o = 4; o; o >>= 1) ss += __shfl_xor_sync(0xffu, ss, o);
        if (t == 0) red[0] = ss;
    }
    __syncthreads();
    float inv = 1.f / fmaxf(sqrtf(red[0]), 1e-12f);
#pragma unroll
    for (int it = 0; it < 3; it++) dst[t + it * 256] = v[it] * inv;
}

// ---------------------------------------------------------------------------
// Kernel 2: denominators
// ---------------------------------------------------------------------------
__global__ void denom_kernel(const int* __restrict__ qm) {
    int q = threadIdx.x;
    if (q < Q) {
        int s = 0;
        for (int i = 1; i < SQ; i++) s += qm[q * SQ + i];
        g_denom[q] = (float)s;
    }
}

// ---------------------------------------------------------------------------
// Kernel 3: projection + l2norm, tf32 mma.sync with cp.async double buffering.
// (unchanged from round 4)
// ---------------------------------------------------------------------------
#define P_SA 36
#define P_SW 132
__global__ __launch_bounds__(256) void proj_kernel(const float* __restrict__ qh,
                                                   const float* __restrict__ ch,
                                                   const float* __restrict__ Wm,
                                                   const float* __restrict__ bias,
                                                   const int*   __restrict__ qm,
                                                   const int*   __restrict__ cm) {
    __shared__ float As[2][64 * P_SA];
    __shared__ float Ws[2][32 * P_SW];
    __shared__ float rowsq[64][4];
    __shared__ float invn[64];
    __shared__ const float* srcp[64];
    __shared__ float mk[64];

    int t = threadIdx.x;
    int w = t >> 5, lane = t & 31, g = lane >> 2, tg = lane & 3;
    int mw = w & 1, nw = w >> 1;
    int m_warp = mw * 32, n_warp = nw * 32;

    if (t < 64) {
        int r = blockIdx.x * 64 + t;
        if (r < QROWS) {
            int q = r / QT, i = r - q * QT;
            srcp[t] = qh + (size_t)(q * SQ + i + 1) * H;
            mk[t]   = (float)qm[q * SQ + i + 1];
        } else {
            int rc = r - QROWS;
            int c = rc / CT, j = rc - c * CT;
            srcp[t] = ch + (size_t)(c * SC + j + 1) * H;
            mk[t]   = (float)cm[c * SC + j + 1];
        }
    }

    float binit[4][2];
#pragma unroll
    for (int nt4 = 0; nt4 < 4; nt4++) {
        int col = n_warp + nt4 * 8 + 2 * tg;
        binit[nt4][0] = bias[col];
        binit[nt4][1] = bias[col + 1];
    }
    __syncthreads();

    uint32_t sA0 = smem_u32(&As[0][0]), sA1 = smem_u32(&As[1][0]);
    uint32_t sW0 = smem_u32(&Ws[0][0]), sW1 = smem_u32(&Ws[1][0]);

#define STAGE(bufA, bufW, KT) do {                                              \
    _Pragma("unroll")                                                           \
    for (int itc = 0; itc < 2; itc++) {                                         \
        int idx = t + itc * 256;                                                \
        int m = idx >> 3, k4 = idx & 7;                                         \
        CP_ASYNC16((bufA) + (m * P_SA + k4 * 4) * 4, srcp[m] + (KT) + k4 * 4);  \
    }                                                                           \
    _Pragma("unroll")                                                           \
    for (int itc = 0; itc < 4; itc++) {                                         \
        int idx = t + itc * 256;                                                \
        int k = idx >> 5, d4 = idx & 31;                                        \
        CP_ASYNC16((bufW) + (k * P_SW + d4 * 4) * 4,                            \
                   Wm + (size_t)((KT) + k) * D + d4 * 4);                       \
    }                                                                           \
} while (0)

    STAGE(sA0, sW0, 0);
    CP_COMMIT();

    float acc[2][4][4];
#pragma unroll
    for (int mt = 0; mt < 2; mt++)
#pragma unroll
        for (int nt4 = 0; nt4 < 4; nt4++)
#pragma unroll
            for (int i = 0; i < 4; i++) acc[mt][nt4][i] = 0.f;

    for (int it = 0; it < 24; it++) {
        if (it < 23) {
            if (it & 1) STAGE(sA0, sW0, (it + 1) * 32);
            else        STAGE(sA1, sW1, (it + 1) * 32);
            CP_COMMIT();
            CP_WAIT1();
        } else {
            CP_WAIT0();
        }
        __syncthreads();
        const float* A = As[it & 1];
        const float* W = Ws[it & 1];
#pragma unroll
        for (int ks = 0; ks < 4; ks++) {
            int k0 = ks * 8;
            uint32_t afr[2][4], bfr[4][2];
#pragma unroll
            for (int mt = 0; mt < 2; mt++) {
                int base = m_warp + mt * 16;
                afr[mt][0] = __float_as_uint(A[(base + g)     * P_SA + k0 + tg]);
                afr[mt][1] = __float_as_uint(A[(base + g + 8) * P_SA + k0 + tg]);
                afr[mt][2] = __float_as_uint(A[(base + g)     * P_SA + k0 + tg + 4]);
                afr[mt][3] = __float_as_uint(A[(base + g + 8) * P_SA + k0 + tg + 4]);
            }
#pragma unroll
            for (int nt4 = 0; nt4 < 4; nt4++) {
                int col = n_warp + nt4 * 8 + g;
                bfr[nt4][0] = __float_as_uint(W[(k0 + tg)     * P_SW + col]);
                bfr[nt4][1] = __float_as_uint(W[(k0 + tg + 4) * P_SW + col]);
            }
#pragma unroll
            for (int mt = 0; mt < 2; mt++)
#pragma unroll
                for (int nt4 = 0; nt4 < 4; nt4++)
                    mma_tf32(acc[mt][nt4], afr[mt], bfr[nt4]);
        }
        __syncthreads();
    }

    float mrow[2][2];
#pragma unroll
    for (int mt = 0; mt < 2; mt++) {
        mrow[mt][0] = mk[m_warp + mt * 16 + g];
        mrow[mt][1] = mk[m_warp + mt * 16 + g + 8];
    }
#pragma unroll
    for (int mt = 0; mt < 2; mt++)
#pragma unroll
        for (int nt4 = 0; nt4 < 4; nt4++)
#pragma unroll
            for (int i = 0; i < 4; i++)
                acc[mt][nt4][i] = mrow[mt][i >> 1] * acc[mt][nt4][i] + binit[nt4][i & 1];

    float pr[2][2];
#pragma unroll
    for (int mt = 0; mt < 2; mt++)
#pragma unroll
        for (int h = 0; h < 2; h++) {
            float s = 0.f;
#pragma unroll
            for (int nt4 = 0; nt4 < 4; nt4++) {
                float c0 = acc[mt][nt4][2 * h], c1 = acc[mt][nt4][2 * h + 1];
                s += c0 * c0 + c1 * c1;
            }
            pr[mt][h] = s;
        }
#pragma unroll
    for (int off = 1; off <= 2; off <<= 1) {
#pragma unroll
        for (int mt = 0; mt < 2; mt++)
#pragma unroll
            for (int h = 0; h < 2; h++)
                pr[mt][h] += __shfl_xor_sync(0xffffffffu, pr[mt][h], off);
    }
    if (tg == 0) {
#pragma unroll
        for (int mt = 0; mt < 2; mt++)
#pragma unroll
            for (int h = 0; h < 2; h++)
                rowsq[m_warp + mt * 16 + g + 8 * h][nw] = pr[mt][h];
    }
    __syncthreads();
    if (t < 64) {
        float s = rowsq[t][0] + rowsq[t][1] + rowsq[t][2] + rowsq[t][3];
        invn[t] = 1.f / fmaxf(sqrtf(s), 1e-12f);
    }
    __syncthreads();

    size_t gbase = (size_t)blockIdx.x * 64;
#pragma unroll
    for (int mt = 0; mt < 2; mt++)
#pragma unroll
        for (int h = 0; h < 2; h++) {
            int r = m_warp + mt * 16 + g + 8 * h;
            float inv = invn[r];
            float* dst = g_col + (gbase + r) * D;
#pragma unroll
            for (int nt4 = 0; nt4 < 4; nt4++) {
                int col = n_warp + nt4 * 8 + 2 * tg;
                float2 v;
                v.x = f2tf(acc[mt][nt4][2 * h]     * inv);
                v.y = f2tf(acc[mt][nt4][2 * h + 1] * inv);
                *(float2*)(dst + col) = v;
            }
        }
#undef STAGE
}

// ---------------------------------------------------------------------------
// Kernel 4: fused maxsim, tf32 mma.sync, DOC-RESIDENT B + STREAMED A tiles.
// Block = (doc c, quarter qq). Grid (256, 4). 512 threads (16 warps).
// B tile (doc, 256x128 padded) loaded ONCE per block; loop over 4 A-tiles
// (4 queries = 124 rows pad 128), cp.async staged.
// Warps: 2(M) x 8(N); warp tile 64x32 (Mt=4, Nt=4), acc 64 regs.
// Per tile: 16 k-slices accumulate, then fused row-max epilogue.
// smem: B 256x132 + A 128x132 + red 8x128 + rowmax = 207360 B, 1 CTA/SM.
// ---------------------------------------------------------------------------
#define MS_SB 132
#define MS_SA 132
#define MSB_FLOATS (256 * MS_SB)
#define MSA_FLOATS (128 * MS_SA)
#define MS_SMEM_FLOATS (MSB_FLOATS + MSA_FLOATS + 8 * 128 + 128)
#define MS_SMEM_BYTES  (MS_SMEM_FLOATS * 4)

__global__ __launch_bounds__(512, 1) void maxsim_kernel(float* __restrict__ out) {
    extern __shared__ float sm[];
    float* Bs     = sm;                       // [n=256][k] stride 132
    float* As     = sm + MSB_FLOATS;          // [m=128][k] stride 132
    float* red    = As + MSA_FLOATS;          // [8][128]
    float* rowmax = red + 8 * 128;            // [128]

    int t = threadIdx.x;
    int w = t >> 5, lane = t & 31, g = lane >> 2, tg = lane & 3;
    int mw = w & 1, nw = w >> 1;              // 2 M-warps, 8 N-warps
    int m_warp = mw * 64, n_warp = nw * 32;

    int c  = blockIdx.x;                      // doc 0..255
    int qq = blockIdx.y;                      // quarter 0..3 (4 qt each)

    // Zero pad rows once: A rows 124..127, B row 255 (k cols 0..127 are read).
    {
        int m = 124 + (t >> 7), k = t & 127;
        As[m * MS_SA + k] = 0.f;
        if (t < 128) Bs[255 * MS_SB + t] = 0.f;
    }

    // Stage B (doc) once: 255 rows x 32 float4 = 8160 chunks.
    const float* bbase = g_col + (size_t)(QROWS + c * CT) * D;
#pragma unroll
    for (int j = 0; j < 16; j++) {
        int idx = t + j * 512;
        if (idx < 8160) {
            int n = idx >> 5, k4 = idx & 31;
            CP_ASYNC16(smem_u32(&Bs[n * MS_SB + k4 * 4]), bbase + (size_t)n * D + k4 * 4);
        }
    }
    CP_COMMIT();

    for (int i = 0; i < 4; i++) {
        int qt = qq * 4 + i;
        // Stage A tile: 124 rows x 32 float4 = 3968 chunks.
        const float* abase = g_col + (size_t)qt * 124 * D;
#pragma unroll
        for (int j = 0; j < 8; j++) {
            int idx = t + j * 512;
            if (idx < 3968) {
                int m = idx >> 5, k4 = idx & 31;
                CP_ASYNC16(smem_u32(&As[m * MS_SA + k4 * 4]), abase + (size_t)m * D + k4 * 4);
            }
        }
        CP_COMMIT();
        CP_WAIT0();
        __syncthreads();

        float acc[4][4][4];
#pragma unroll
        for (int mt = 0; mt < 4; mt++)
#pragma unroll
            for (int nt = 0; nt < 4; nt++)
#pragma unroll
                for (int k = 0; k < 4; k++) acc[mt][nt][k] = 0.f;

#pragma unroll 2
        for (int ks = 0; ks < 16; ks++) {
            int k0 = ks * 8;
            uint32_t afr[4][4], bfr[4][2];
#pragma unroll
            for (int mt = 0; mt < 4; mt++) {
                int base = m_warp + mt * 16;
                afr[mt][0] = __float_as_uint(As[(base + g)     * MS_SA + k0 + tg]);
                afr[mt][1] = __float_as_uint(As[(base + g + 8) * MS_SA + k0 + tg]);
                afr[mt][2] = __float_as_uint(As[(base + g)     * MS_SA + k0 + tg + 4]);
                afr[mt][3] = __float_as_uint(As[(base + g + 8) * MS_SA + k0 + tg + 4]);
            }
#pragma unroll
            for (int nt = 0; nt < 4; nt++) {
                int n = n_warp + nt * 8 + g;
                bfr[nt][0] = __float_as_uint(Bs[n * MS_SB + k0 + tg]);
                bfr[nt][1] = __float_as_uint(Bs[n * MS_SB + k0 + tg + 4]);
            }
#pragma unroll
            for (int mt = 0; mt < 4; mt++)
#pragma unroll
                for (int nt = 0; nt < 4; nt++)
                    mma_tf32(acc[mt][nt], afr[mt], bfr[nt]);
        }

        // Fused row-max (guard padded col j=255; padded rows harmless).
        float rp[4][2];
#pragma unroll
        for (int mt = 0; mt < 4; mt++) { rp[mt][0] = -INFINITY; rp[mt][1] = -INFINITY; }
#pragma unroll
        for (int mt = 0; mt < 4; mt++)
#pragma unroll
            for (int nt = 0; nt < 4; nt++)
#pragma unroll
                for (int k = 0; k < 4; k++) {
                    int j = n_warp + nt * 8 + 2 * tg + (k & 1);
                    if (j < CT) rp[mt][k >> 1] = fmaxf(rp[mt][k >> 1], acc[mt][nt][k]);
                }
#pragma unroll
        for (int off = 1; off <= 2; off <<= 1)
#pragma unroll
            for (int mt = 0; mt < 4; mt++)
#pragma unroll
                for (int h = 0; h < 2; h++)
                    rp[mt][h] = fmaxf(rp[mt][h], __shfl_xor_sync(0xffffffffu, rp[mt][h], off));
        if (tg == 0) {
#pragma unroll
            for (int mt = 0; mt < 4; mt++)
#pragma unroll
                for (int h = 0; h < 2; h++)
                    red[nw * 128 + m_warp + mt * 16 + g + 8 * h] = rp[mt][h];
        }
        __syncthreads();
        if (t < 124) {
            float mx = red[t];
#pragma unroll
            for (int r8 = 1; r8 < 8; r8++) mx = fmaxf(mx, red[r8 * 128 + t]);
            rowmax[t] = mx;
        }
        __syncthreads();
        if (t < 4) {
            int q = qt * 4 + t;
            float s = 0.f;
#pragma unroll
            for (int k = 0; k < 31; k++) s += rowmax[t * 31 + k];
            out[q * CC + c] = s / g_denom[q];
        }
        __syncthreads();   // red/rowmax/As reusable next tile
    }
}

// ---------------------------------------------------------------------------
extern "C" void kernel_launch(void* const* d_in, const int* in_sizes, int n_in,
                              void* d_out, int out_size) {
    const float* qh  = (const float*)d_in[0];
    const float* ch  = (const float*)d_in[1];
    const float* Wm  = (const float*)d_in[2];
    const float* bia = (const float*)d_in[3];
    const int*   qm  = (const int*)d_in[4];
    const int*   cm  = (const int*)d_in[5];
    float* out = (float*)d_out;

    cudaFuncSetAttribute(maxsim_kernel,
                         cudaFuncAttributeMaxDynamicSharedMemorySize,
                         MS_SMEM_BYTES);

    pooled_kernel<<<Q + CC, 256>>>(qh, ch, qm, cm, out);
    denom_kernel<<<1, 64>>>(qm);
    proj_kernel<<<NROWS / 64, 256>>>(qh, ch, Wm, bia, qm, cm);
    maxsim_kernel<<<dim3(256, 4), 512, MS_SMEM_BYTES>>>(out);
}